// round 2
// baseline (speedup 1.0000x reference)
#include <cuda_runtime.h>
#include <cuda_bf16.h>
#include <math.h>

// ---------------------------------------------------------------------------
// Problem constants
// ---------------------------------------------------------------------------
#define N_NODES 102400
#define N_EDGES 1638400
#define IN_DIM  16
#define GNN_H   64
#define RNN_H   128
#define GATE4   512      // 4*RNN_H
#define OUT_DIM 7
#define SEQ_LEN 50
#define BATCH   (N_NODES / SEQ_LEN)   // 2048

// ---------------------------------------------------------------------------
// Scratch (static device globals; no allocation allowed)
// ---------------------------------------------------------------------------
__device__ float g_dinv[N_NODES];                    // 0.4 MB
__device__ float g_xw  [N_NODES * GNN_H];            // 26 MB
__device__ float g_acc [N_NODES * GNN_H];            // 26 MB
__device__ float g_h   [N_NODES * GNN_H];            // 26 MB
__device__ float g_pre [(size_t)N_NODES * GATE4];    // 210 MB
__device__ float g_hseq[(size_t)N_NODES * RNN_H];    // 52 MB
__device__ float g_hstate[BATCH * RNN_H];
__device__ float g_cstate[BATCH * RNN_H];
__device__ float g_wihT[RNN_H * GATE4];              // max 128x512
__device__ float g_whhT[RNN_H * GATE4];

// ---------------------------------------------------------------------------
// Degree / normalization
// ---------------------------------------------------------------------------
__global__ void k_fill(float* p, float v, int n) {
    int i = blockIdx.x * blockDim.x + threadIdx.x;
    if (i < n) p[i] = v;
}

// NOTE: edge_index is int32 on device (JAX demotes int64 without x64 mode).
__global__ void k_deg_count(const int* __restrict__ ei, float* __restrict__ deg) {
    int e = blockIdx.x * blockDim.x + threadIdx.x;
    if (e >= N_EDGES) return;
    int d = ei[N_EDGES + e];
    atomicAdd(&deg[d], 1.0f);
}

__global__ void k_rsqrt(float* p, int n) {
    int i = blockIdx.x * blockDim.x + threadIdx.x;
    if (i < n) p[i] = rsqrtf(p[i]);
}

// ---------------------------------------------------------------------------
// GCN dense part: out[N,64] = X[N,K] @ W[K,64]
// 512 threads, 16 rows/block, each thread computes 2 outputs.
// ---------------------------------------------------------------------------
template<int K>
__global__ __launch_bounds__(512) void k_gcn_mm(const float* __restrict__ X,
                                                const float* __restrict__ W,
                                                float* __restrict__ out) {
    __shared__ float sW[K * 64];
    __shared__ float sX[16 * K];
    int tid = threadIdx.x;
    size_t row0 = (size_t)blockIdx.x * 16;
    for (int i = tid; i < K * 64; i += 512) sW[i] = W[i];
    for (int i = tid; i < 16 * K; i += 512) sX[i] = X[row0 * K + i];
    __syncthreads();
    int r = tid >> 6;       // 0..7
    int c = tid & 63;
    float a0 = 0.f, a1 = 0.f;
#pragma unroll
    for (int k = 0; k < K; ++k) {
        float w = sW[k * 64 + c];
        a0 = fmaf(sX[r * K + k],        w, a0);
        a1 = fmaf(sX[(r + 8) * K + k],  w, a1);
    }
    out[(row0 + r) * 64 + c]     = a0;
    out[(row0 + r + 8) * 64 + c] = a1;
}

// acc[n,c] = xw[n,c]*dinv[n]^2 + bias[c]   (self-loop + bias init)
__global__ void k_selfloop_init(const float* __restrict__ xw, const float* __restrict__ dinv,
                                const float* __restrict__ bias, float* __restrict__ acc) {
    size_t i = (size_t)blockIdx.x * blockDim.x + threadIdx.x;
    if (i >= (size_t)N_NODES * 64) return;
    int n = (int)(i >> 6);
    int c = (int)(i & 63);
    float dv = dinv[n];
    acc[i] = xw[i] * dv * dv + bias[c];
}

// scatter: one warp per edge, each lane handles 2 consecutive columns
__global__ void k_scatter(const int* __restrict__ ei, const float* __restrict__ dinv,
                          const float* __restrict__ hx, float* __restrict__ acc) {
    unsigned gid = blockIdx.x * blockDim.x + threadIdx.x;
    unsigned e = gid >> 5;
    if (e >= N_EDGES) return;
    int pair = gid & 31;
    int s = ei[e];
    int d = ei[N_EDGES + e];
    float nrm = dinv[s] * dinv[d];
    float2 v = *(const float2*)&hx[(size_t)s * 64 + pair * 2];
    atomicAdd(&acc[(size_t)d * 64 + pair * 2 + 0], v.x * nrm);
    atomicAdd(&acc[(size_t)d * 64 + pair * 2 + 1], v.y * nrm);
}

__global__ void k_relu(const float* __restrict__ a, float* __restrict__ o, size_t n) {
    size_t i = (size_t)blockIdx.x * blockDim.x + threadIdx.x;
    if (i < n) o[i] = fmaxf(a[i], 0.f);
}

// ---------------------------------------------------------------------------
// transpose [R,C] -> [C,R]
// ---------------------------------------------------------------------------
__global__ void k_transpose(const float* __restrict__ in, float* __restrict__ out, int R, int C) {
    int i = blockIdx.x * blockDim.x + threadIdx.x;
    if (i >= R * C) return;
    int r = i / C, c = i % C;
    out[c * R + r] = in[i];
}

// ---------------------------------------------------------------------------
// pre = A[M,K] @ Bt[K,512] + bih + bhh     (register-tiled fp32 GEMM)
// BM=64, BN=128, BK=16, 256 threads, 8x4 microtile
// ---------------------------------------------------------------------------
#define GM_BM 64
#define GM_BN 128
#define GM_BK 16
__global__ __launch_bounds__(256) void k_gemm_pre(const float* __restrict__ A,
                                                  const float* __restrict__ Bt,
                                                  const float* __restrict__ b1,
                                                  const float* __restrict__ b2,
                                                  float* __restrict__ C, int K) {
    __shared__ float As[GM_BK][GM_BM];
    __shared__ float Bs[GM_BK][GM_BN];
    size_t bm = (size_t)blockIdx.x * GM_BM;
    int bn = blockIdx.y * GM_BN;
    int tid = threadIdx.x;
    int tn0 = (tid & 31) * 4;    // TN=4
    int tm0 = (tid >> 5) * 8;    // TM=8
    float acc[8][4];
#pragma unroll
    for (int i = 0; i < 8; ++i)
#pragma unroll
        for (int j = 0; j < 4; ++j) acc[i][j] = 0.f;

    for (int k0 = 0; k0 < K; k0 += GM_BK) {
        {   // A tile: 64x16, float4 per thread
            int ar = tid >> 2, ak = (tid & 3) * 4;
            float4 a4 = *(const float4*)&A[(bm + ar) * K + k0 + ak];
            As[ak + 0][ar] = a4.x; As[ak + 1][ar] = a4.y;
            As[ak + 2][ar] = a4.z; As[ak + 3][ar] = a4.w;
        }
#pragma unroll
        for (int p = 0; p < 2; ++p) {   // B tile: 16x128
            int bk = p * 8 + (tid >> 5);
            int bc = (tid & 31) * 4;
            *(float4*)&Bs[bk][bc] = *(const float4*)&Bt[(size_t)(k0 + bk) * GATE4 + bn + bc];
        }
        __syncthreads();
#pragma unroll
        for (int kk = 0; kk < GM_BK; ++kk) {
            float4 a0 = *(const float4*)&As[kk][tm0];
            float4 a1 = *(const float4*)&As[kk][tm0 + 4];
            float4 bv = *(const float4*)&Bs[kk][tn0];
            float av[8] = {a0.x, a0.y, a0.z, a0.w, a1.x, a1.y, a1.z, a1.w};
            float bb[4] = {bv.x, bv.y, bv.z, bv.w};
#pragma unroll
            for (int i = 0; i < 8; ++i)
#pragma unroll
                for (int j = 0; j < 4; ++j)
                    acc[i][j] = fmaf(av[i], bb[j], acc[i][j]);
        }
        __syncthreads();
    }
    float bias[4];
#pragma unroll
    for (int j = 0; j < 4; ++j) bias[j] = b1[bn + tn0 + j] + b2[bn + tn0 + j];
#pragma unroll
    for (int i = 0; i < 8; ++i) {
        size_t row = bm + tm0 + i;
#pragma unroll
        for (int j = 0; j < 4; ++j)
            C[row * GATE4 + bn + tn0 + j] = acc[i][j] + bias[j];
    }
}

// ---------------------------------------------------------------------------
// LSTM recurrent step: gates = pre[:,t,:] + h @ whhT ; activations ; update
// 128 blocks x 128 threads, SBM=16 batch rows per block (one wave).
// ---------------------------------------------------------------------------
#define SBM 16
__global__ __launch_bounds__(128) void k_lstm_step(const float* __restrict__ pre,
                                                   const float* __restrict__ whhT,
                                                   float* __restrict__ hstate,
                                                   float* __restrict__ cstate,
                                                   float* __restrict__ hseq, int t) {
    __shared__ float sh[SBM * RNN_H];
    int j = threadIdx.x;            // 0..127 = hidden unit
    int b0 = blockIdx.x * SBM;
    for (int i = j; i < SBM * RNN_H; i += 128) sh[i] = hstate[b0 * RNN_H + i];
    __syncthreads();

    float aI[SBM], aF[SBM], aG[SBM], aO[SBM];
#pragma unroll
    for (int r = 0; r < SBM; ++r) {
        const float* p = pre + ((size_t)(b0 + r) * SEQ_LEN + t) * GATE4;
        aI[r] = p[j]; aF[r] = p[128 + j]; aG[r] = p[256 + j]; aO[r] = p[384 + j];
    }
    for (int k = 0; k < RNN_H; ++k) {
        const float* w = whhT + (size_t)k * GATE4;
        float wI = w[j], wF = w[128 + j], wG = w[256 + j], wO = w[384 + j];
#pragma unroll
        for (int r = 0; r < SBM; ++r) {
            float hk = sh[r * RNN_H + k];
            aI[r] = fmaf(hk, wI, aI[r]);
            aF[r] = fmaf(hk, wF, aF[r]);
            aG[r] = fmaf(hk, wG, aG[r]);
            aO[r] = fmaf(hk, wO, aO[r]);
        }
    }
#pragma unroll
    for (int r = 0; r < SBM; ++r) {
        int bi = b0 + r;
        float c  = cstate[bi * RNN_H + j];
        float ig = 1.f / (1.f + expf(-aI[r]));
        float fg = 1.f / (1.f + expf(-aF[r]));
        float gg = tanhf(aG[r]);
        float og = 1.f / (1.f + expf(-aO[r]));
        c = fg * c + ig * gg;
        float h = og * tanhf(c);
        cstate[bi * RNN_H + j] = c;
        hstate[bi * RNN_H + j] = h;
        if (hseq) hseq[((size_t)bi * SEQ_LEN + t) * RNN_H + j] = h;
    }
}

// ---------------------------------------------------------------------------
// FC head: out[B,7] = h[B,128] @ fcw[128,7] + fcb
// ---------------------------------------------------------------------------
__global__ void k_fc(const float* __restrict__ h, const float* __restrict__ w,
                     const float* __restrict__ b, float* __restrict__ out) {
    int i = blockIdx.x * blockDim.x + threadIdx.x;
    if (i >= BATCH * OUT_DIM) return;
    int bb = i / OUT_DIM, o = i % OUT_DIM;
    float acc = b[o];
#pragma unroll 4
    for (int k = 0; k < RNN_H; ++k)
        acc = fmaf(h[bb * RNN_H + k], w[k * OUT_DIM + o], acc);
    out[i] = acc;
}

// ---------------------------------------------------------------------------
// Host launcher
// ---------------------------------------------------------------------------
extern "C" void kernel_launch(void* const* d_in, const int* in_sizes, int n_in,
                              void* d_out, int out_size) {
    // inputs: x, edge_index, [seq_len], w1,b1,w2,b2, wih0,whh0,bih0,bhh0,
    //         wih1,whh1,bih1,bhh1, fcw,fcb
    const float* x  = (const float*)d_in[0];
    const int*   ei = (const int*)d_in[1];   // int32 (JAX demotes int64)
    int w1i = n_in - 14;   // robust to seq_len being present or not
    const float* w1   = (const float*)d_in[w1i + 0];
    const float* b1   = (const float*)d_in[w1i + 1];
    const float* w2   = (const float*)d_in[w1i + 2];
    const float* b2   = (const float*)d_in[w1i + 3];
    const float* wih0 = (const float*)d_in[w1i + 4];
    const float* whh0 = (const float*)d_in[w1i + 5];
    const float* bih0 = (const float*)d_in[w1i + 6];
    const float* bhh0 = (const float*)d_in[w1i + 7];
    const float* wih1 = (const float*)d_in[w1i + 8];
    const float* whh1 = (const float*)d_in[w1i + 9];
    const float* bih1 = (const float*)d_in[w1i + 10];
    const float* bhh1 = (const float*)d_in[w1i + 11];
    const float* fcw  = (const float*)d_in[w1i + 12];
    const float* fcb  = (const float*)d_in[w1i + 13];
    float* out = (float*)d_out;

    float *dinv, *xw, *acc, *h, *pre, *hseq, *hstate, *cstate, *wihT, *whhT;
    cudaGetSymbolAddress((void**)&dinv,   g_dinv);
    cudaGetSymbolAddress((void**)&xw,     g_xw);
    cudaGetSymbolAddress((void**)&acc,    g_acc);
    cudaGetSymbolAddress((void**)&h,      g_h);
    cudaGetSymbolAddress((void**)&pre,    g_pre);
    cudaGetSymbolAddress((void**)&hseq,   g_hseq);
    cudaGetSymbolAddress((void**)&hstate, g_hstate);
    cudaGetSymbolAddress((void**)&cstate, g_cstate);
    cudaGetSymbolAddress((void**)&wihT,   g_wihT);
    cudaGetSymbolAddress((void**)&whhT,   g_whhT);

    const int T256 = 256;
    // --- degree / normalization ---
    k_fill<<<(N_NODES + T256 - 1) / T256, T256>>>(dinv, 1.0f, N_NODES);
    k_deg_count<<<(N_EDGES + T256 - 1) / T256, T256>>>(ei, dinv);
    k_rsqrt<<<(N_NODES + T256 - 1) / T256, T256>>>(dinv, N_NODES);

    size_t nh = (size_t)N_NODES * 64;
    unsigned scat_blocks = (unsigned)(((size_t)N_EDGES * 32 + T256 - 1) / T256);

    // --- GCN layer 1 ---
    k_gcn_mm<IN_DIM><<<N_NODES / 16, 512>>>(x, w1, xw);
    k_selfloop_init<<<(unsigned)((nh + T256 - 1) / T256), T256>>>(xw, dinv, b1, acc);
    k_scatter<<<scat_blocks, T256>>>(ei, dinv, xw, acc);
    k_relu<<<(unsigned)((nh + T256 - 1) / T256), T256>>>(acc, h, nh);

    // --- GCN layer 2 ---
    k_gcn_mm<GNN_H><<<N_NODES / 16, 512>>>(h, w2, xw);
    k_selfloop_init<<<(unsigned)((nh + T256 - 1) / T256), T256>>>(xw, dinv, b2, acc);
    k_scatter<<<scat_blocks, T256>>>(ei, dinv, xw, acc);
    k_relu<<<(unsigned)((nh + T256 - 1) / T256), T256>>>(acc, h, nh);

    // --- LSTM layer 0 ---
    k_transpose<<<(GATE4 * GNN_H + T256 - 1) / T256, T256>>>(wih0, wihT, GATE4, GNN_H);
    {
        dim3 grid(N_NODES / GM_BM, GATE4 / GM_BN);
        k_gemm_pre<<<grid, 256>>>(h, wihT, bih0, bhh0, pre, GNN_H);
    }
    k_transpose<<<(GATE4 * RNN_H + T256 - 1) / T256, T256>>>(whh0, whhT, GATE4, RNN_H);
    k_fill<<<(BATCH * RNN_H + T256 - 1) / T256, T256>>>(hstate, 0.f, BATCH * RNN_H);
    k_fill<<<(BATCH * RNN_H + T256 - 1) / T256, T256>>>(cstate, 0.f, BATCH * RNN_H);
    for (int t = 0; t < SEQ_LEN; ++t)
        k_lstm_step<<<BATCH / SBM, 128>>>(pre, whhT, hstate, cstate, hseq, t);

    // --- LSTM layer 1 ---
    k_transpose<<<(GATE4 * RNN_H + T256 - 1) / T256, T256>>>(wih1, wihT, GATE4, RNN_H);
    {
        dim3 grid(N_NODES / GM_BM, GATE4 / GM_BN);
        k_gemm_pre<<<grid, 256>>>(hseq, wihT, bih1, bhh1, pre, RNN_H);
    }
    k_transpose<<<(GATE4 * RNN_H + T256 - 1) / T256, T256>>>(whh1, whhT, GATE4, RNN_H);
    k_fill<<<(BATCH * RNN_H + T256 - 1) / T256, T256>>>(hstate, 0.f, BATCH * RNN_H);
    k_fill<<<(BATCH * RNN_H + T256 - 1) / T256, T256>>>(cstate, 0.f, BATCH * RNN_H);
    for (int t = 0; t < SEQ_LEN; ++t)
        k_lstm_step<<<BATCH / SBM, 128>>>(pre, whhT, hstate, cstate, (float*)nullptr, t);

    // --- FC head ---
    k_fc<<<(BATCH * OUT_DIM + T256 - 1) / T256, T256>>>(hstate, fcw, fcb, out);
}

// round 4
// speedup vs baseline: 2.1555x; 2.1555x over previous
#include <cuda_runtime.h>
#include <cuda_bf16.h>
#include <math.h>

// ---------------------------------------------------------------------------
// Problem constants
// ---------------------------------------------------------------------------
#define N_NODES 102400
#define N_EDGES 1638400
#define IN_DIM  16
#define GNN_H   64
#define RNN_H   128
#define GATE4   512
#define OUT_DIM 7
#define SEQ_LEN 50
#define BATCH   (N_NODES / SEQ_LEN)   // 2048

#define SCAN_T  512
#define SCAN_NB (N_NODES / SCAN_T)    // 200

// ---------------------------------------------------------------------------
// Scratch (static device globals)
// ---------------------------------------------------------------------------
__device__ float g_dinv[N_NODES];
__device__ int   g_deg [N_NODES];
__device__ int   g_cur [N_NODES];
__device__ int   g_off [N_NODES + 1];
__device__ int   g_boff[SCAN_NB];
__device__ int   g_csr_src[N_EDGES];
__device__ float g_csr_nrm[N_EDGES];
__device__ float g_xw  [N_NODES * GNN_H];            // 26 MB
__device__ float g_h   [N_NODES * GNN_H];            // 26 MB
__device__ float g_pre [(size_t)N_NODES * GATE4];    // 210 MB
__device__ float g_hseq[(size_t)N_NODES * RNN_H];    // 52 MB
__device__ float g_hstate[BATCH * RNN_H];
__device__ float g_wihT[RNN_H * GATE4];
__device__ float g_whhT[RNN_H * GATE4];

// ---------------------------------------------------------------------------
// CSR build: degree -> prefix scan -> fill
// ---------------------------------------------------------------------------
__global__ void k_zero_int(int* p, int n) {
    int i = blockIdx.x * blockDim.x + threadIdx.x;
    if (i < n) p[i] = 0;
}

__global__ void k_deg_int(const int* __restrict__ ei, int* __restrict__ deg) {
    int e = blockIdx.x * blockDim.x + threadIdx.x;
    if (e >= N_EDGES) return;
    atomicAdd(&deg[ei[N_EDGES + e]], 1);
}

__global__ void k_dinv(const int* __restrict__ deg, float* __restrict__ dinv) {
    int i = blockIdx.x * blockDim.x + threadIdx.x;
    if (i < N_NODES) dinv[i] = rsqrtf((float)(deg[i] + 1));   // +1 self loop
}

__global__ __launch_bounds__(SCAN_T) void k_scan_blocksum(const int* __restrict__ deg,
                                                          int* __restrict__ bsum) {
    __shared__ int s[SCAN_T];
    int i = threadIdx.x;
    s[i] = deg[blockIdx.x * SCAN_T + i];
    __syncthreads();
    for (int d = SCAN_T / 2; d > 0; d >>= 1) {
        if (i < d) s[i] += s[i + d];
        __syncthreads();
    }
    if (i == 0) bsum[blockIdx.x] = s[0];
}

__global__ void k_scan_aux(int* __restrict__ bsum, int* __restrict__ boff, int* __restrict__ off) {
    if (threadIdx.x == 0) {
        int run = 0;
        for (int b = 0; b < SCAN_NB; ++b) { int v = bsum[b]; boff[b] = run; run += v; }
        off[N_NODES] = run;   // == N_EDGES
    }
}

__global__ __launch_bounds__(SCAN_T) void k_scan_write(const int* __restrict__ deg,
                                                       const int* __restrict__ boff,
                                                       int* __restrict__ off) {
    __shared__ int s[SCAN_T];
    int i = threadIdx.x;
    int g = blockIdx.x * SCAN_T + i;
    int my = deg[g];
    s[i] = my;
    __syncthreads();
    for (int d = 1; d < SCAN_T; d <<= 1) {
        int v = (i >= d) ? s[i - d] : 0;
        __syncthreads();
        s[i] += v;
        __syncthreads();
    }
    off[g] = boff[blockIdx.x] + s[i] - my;   // exclusive
}

__global__ void k_csr_fill(const int* __restrict__ ei, const int* __restrict__ off,
                           int* __restrict__ cur, const float* __restrict__ dinv,
                           int* __restrict__ csr_src, float* __restrict__ csr_nrm) {
    int e = blockIdx.x * blockDim.x + threadIdx.x;
    if (e >= N_EDGES) return;
    int s = ei[e];
    int d = ei[N_EDGES + e];
    int pos = off[d] + atomicAdd(&cur[d], 1);
    csr_src[pos] = s;
    csr_nrm[pos] = dinv[s] * dinv[d];
}

// ---------------------------------------------------------------------------
// GCN dense part: out[N,64] = X[N,K] @ W[K,64]
// ---------------------------------------------------------------------------
template<int K>
__global__ __launch_bounds__(512) void k_gcn_mm(const float* __restrict__ X,
                                                const float* __restrict__ W,
                                                float* __restrict__ out) {
    __shared__ float sW[K * 64];
    __shared__ float sX[16 * K];
    int tid = threadIdx.x;
    size_t row0 = (size_t)blockIdx.x * 16;
    for (int i = tid; i < K * 64; i += 512) sW[i] = W[i];
    for (int i = tid; i < 16 * K; i += 512) sX[i] = X[row0 * K + i];
    __syncthreads();
    int r = tid >> 6;
    int c = tid & 63;
    float a0 = 0.f, a1 = 0.f;
#pragma unroll
    for (int k = 0; k < K; ++k) {
        float w = sW[k * 64 + c];
        a0 = fmaf(sX[r * K + k],       w, a0);
        a1 = fmaf(sX[(r + 8) * K + k], w, a1);
    }
    out[(row0 + r) * 64 + c]     = a0;
    out[(row0 + r + 8) * 64 + c] = a1;
}

// ---------------------------------------------------------------------------
// Fused gather + self-loop + bias + relu.
// One warp per destination node; lane handles 2 consecutive columns (float2).
// ---------------------------------------------------------------------------
__global__ __launch_bounds__(256) void k_gather(const int* __restrict__ off,
                                                const int* __restrict__ csr_src,
                                                const float* __restrict__ csr_nrm,
                                                const float* __restrict__ xw,
                                                const float* __restrict__ dinv,
                                                const float* __restrict__ bias,
                                                float* __restrict__ out) {
    int warp = (blockIdx.x * 256 + threadIdx.x) >> 5;
    int lane = threadIdx.x & 31;
    if (warp >= N_NODES) return;
    int d = warp;
    int c0 = lane * 2;
    float dv = dinv[d];
    float2 self = *(const float2*)&xw[(size_t)d * 64 + c0];
    float2 bb   = *(const float2*)&bias[c0];
    float accx = self.x * dv * dv + bb.x;
    float accy = self.y * dv * dv + bb.y;
    int e0 = off[d], e1 = off[d + 1];
    for (int e = e0; e < e1; ++e) {
        int   s   = csr_src[e];
        float nrm = csr_nrm[e];
        float2 v = *(const float2*)&xw[(size_t)s * 64 + c0];
        accx = fmaf(v.x, nrm, accx);
        accy = fmaf(v.y, nrm, accy);
    }
    float2 o; o.x = fmaxf(accx, 0.f); o.y = fmaxf(accy, 0.f);
    *(float2*)&out[(size_t)d * 64 + c0] = o;
}

// ---------------------------------------------------------------------------
// transpose [R,C] -> [C,R]
// ---------------------------------------------------------------------------
__global__ void k_transpose(const float* __restrict__ in, float* __restrict__ out, int R, int C) {
    int i = blockIdx.x * blockDim.x + threadIdx.x;
    if (i >= R * C) return;
    int r = i / C, c = i % C;
    out[c * R + r] = in[i];
}

// ---------------------------------------------------------------------------
// pre = A[M,K] @ Bt[K,512] + bih + bhh
// ---------------------------------------------------------------------------
#define GM_BM 64
#define GM_BN 128
#define GM_BK 16
__global__ __launch_bounds__(256) void k_gemm_pre(const float* __restrict__ A,
                                                  const float* __restrict__ Bt,
                                                  const float* __restrict__ b1,
                                                  const float* __restrict__ b2,
                                                  float* __restrict__ C, int K) {
    __shared__ float As[GM_BK][GM_BM];
    __shared__ float Bs[GM_BK][GM_BN];
    size_t bm = (size_t)blockIdx.x * GM_BM;
    int bn = blockIdx.y * GM_BN;
    int tid = threadIdx.x;
    int tn0 = (tid & 31) * 4;
    int tm0 = (tid >> 5) * 8;
    float acc[8][4];
#pragma unroll
    for (int i = 0; i < 8; ++i)
#pragma unroll
        for (int j = 0; j < 4; ++j) acc[i][j] = 0.f;

    for (int k0 = 0; k0 < K; k0 += GM_BK) {
        {
            int ar = tid >> 2, ak = (tid & 3) * 4;
            float4 a4 = *(const float4*)&A[(bm + ar) * K + k0 + ak];
            As[ak + 0][ar] = a4.x; As[ak + 1][ar] = a4.y;
            As[ak + 2][ar] = a4.z; As[ak + 3][ar] = a4.w;
        }
#pragma unroll
        for (int p = 0; p < 2; ++p) {
            int bk = p * 8 + (tid >> 5);
            int bc = (tid & 31) * 4;
            *(float4*)&Bs[bk][bc] = *(const float4*)&Bt[(size_t)(k0 + bk) * GATE4 + bn + bc];
        }
        __syncthreads();
#pragma unroll
        for (int kk = 0; kk < GM_BK; ++kk) {
            float4 a0 = *(const float4*)&As[kk][tm0];
            float4 a1 = *(const float4*)&As[kk][tm0 + 4];
            float4 bv = *(const float4*)&Bs[kk][tn0];
            float av[8] = {a0.x, a0.y, a0.z, a0.w, a1.x, a1.y, a1.z, a1.w};
            float bb[4] = {bv.x, bv.y, bv.z, bv.w};
#pragma unroll
            for (int i = 0; i < 8; ++i)
#pragma unroll
                for (int j = 0; j < 4; ++j)
                    acc[i][j] = fmaf(av[i], bb[j], acc[i][j]);
        }
        __syncthreads();
    }
    float bias[4];
#pragma unroll
    for (int j = 0; j < 4; ++j) bias[j] = b1[bn + tn0 + j] + b2[bn + tn0 + j];
#pragma unroll
    for (int i = 0; i < 8; ++i) {
        size_t row = bm + tm0 + i;
#pragma unroll
        for (int j = 0; j < 4; ++j)
            C[row * GATE4 + bn + tn0 + j] = acc[i][j] + bias[j];
    }
}

// ---------------------------------------------------------------------------
// Persistent LSTM layer: one block owns SBM batch rows for ALL timesteps.
// 128 blocks x 128 threads; thread j = hidden column j.
// ---------------------------------------------------------------------------
#define SBM 16
__global__ __launch_bounds__(128) void k_lstm_layer(const float* __restrict__ pre,
                                                    const float* __restrict__ whhT,
                                                    float* __restrict__ hseq,
                                                    float* __restrict__ hlast) {
    __shared__ float sh[SBM * RNN_H];
    int j = threadIdx.x;
    int b0 = blockIdx.x * SBM;
    float c[SBM];
#pragma unroll
    for (int r = 0; r < SBM; ++r) c[r] = 0.f;
    for (int i = j; i < SBM * RNN_H; i += 128) sh[i] = 0.f;
    __syncthreads();

    for (int t = 0; t < SEQ_LEN; ++t) {
        float aI[SBM], aF[SBM], aG[SBM], aO[SBM];
#pragma unroll
        for (int r = 0; r < SBM; ++r) {
            const float* p = pre + ((size_t)(b0 + r) * SEQ_LEN + t) * GATE4;
            aI[r] = p[j]; aF[r] = p[128 + j]; aG[r] = p[256 + j]; aO[r] = p[384 + j];
        }
#pragma unroll 2
        for (int k = 0; k < RNN_H; ++k) {
            const float* w = whhT + (size_t)k * GATE4;
            float wI = w[j], wF = w[128 + j], wG = w[256 + j], wO = w[384 + j];
#pragma unroll
            for (int r = 0; r < SBM; ++r) {
                float hk = sh[r * RNN_H + k];
                aI[r] = fmaf(hk, wI, aI[r]);
                aF[r] = fmaf(hk, wF, aF[r]);
                aG[r] = fmaf(hk, wG, aG[r]);
                aO[r] = fmaf(hk, wO, aO[r]);
            }
        }
        __syncthreads();   // all sh reads done before overwrite
#pragma unroll
        for (int r = 0; r < SBM; ++r) {
            float ig = 1.f / (1.f + expf(-aI[r]));
            float fg = 1.f / (1.f + expf(-aF[r]));
            float gg = tanhf(aG[r]);
            float og = 1.f / (1.f + expf(-aO[r]));
            float cc = fg * c[r] + ig * gg;
            float hh = og * tanhf(cc);
            c[r] = cc;
            sh[r * RNN_H + j] = hh;
            if (hseq) hseq[((size_t)(b0 + r) * SEQ_LEN + t) * RNN_H + j] = hh;
        }
        __syncthreads();
    }
#pragma unroll
    for (int r = 0; r < SBM; ++r)
        hlast[(b0 + r) * RNN_H + j] = sh[r * RNN_H + j];
}

// ---------------------------------------------------------------------------
// FC head
// ---------------------------------------------------------------------------
__global__ void k_fc(const float* __restrict__ h, const float* __restrict__ w,
                     const float* __restrict__ b, float* __restrict__ out) {
    int i = blockIdx.x * blockDim.x + threadIdx.x;
    if (i >= BATCH * OUT_DIM) return;
    int bb = i / OUT_DIM, o = i % OUT_DIM;
    float acc = b[o];
#pragma unroll 4
    for (int k = 0; k < RNN_H; ++k)
        acc = fmaf(h[bb * RNN_H + k], w[k * OUT_DIM + o], acc);
    out[i] = acc;
}

// ---------------------------------------------------------------------------
// Host launcher
// ---------------------------------------------------------------------------
extern "C" void kernel_launch(void* const* d_in, const int* in_sizes, int n_in,
                              void* d_out, int out_size) {
    const float* x  = (const float*)d_in[0];
    const int*   ei = (const int*)d_in[1];   // int32 on device
    int w1i = n_in - 14;
    const float* w1   = (const float*)d_in[w1i + 0];
    const float* b1   = (const float*)d_in[w1i + 1];
    const float* w2   = (const float*)d_in[w1i + 2];
    const float* b2   = (const float*)d_in[w1i + 3];
    const float* wih0 = (const float*)d_in[w1i + 4];
    const float* whh0 = (const float*)d_in[w1i + 5];
    const float* bih0 = (const float*)d_in[w1i + 6];
    const float* bhh0 = (const float*)d_in[w1i + 7];
    const float* wih1 = (const float*)d_in[w1i + 8];
    const float* whh1 = (const float*)d_in[w1i + 9];
    const float* bih1 = (const float*)d_in[w1i + 10];
    const float* bhh1 = (const float*)d_in[w1i + 11];
    const float* fcw  = (const float*)d_in[w1i + 12];
    const float* fcb  = (const float*)d_in[w1i + 13];
    float* out = (float*)d_out;

    float *dinv, *xw, *h, *pre, *hseq, *hstate, *wihT, *whhT, *csr_nrm;
    int *deg, *cur, *off, *boff, *csr_src;
    cudaGetSymbolAddress((void**)&dinv,    g_dinv);
    cudaGetSymbolAddress((void**)&deg,     g_deg);
    cudaGetSymbolAddress((void**)&cur,     g_cur);
    cudaGetSymbolAddress((void**)&off,     g_off);
    cudaGetSymbolAddress((void**)&boff,    g_boff);
    cudaGetSymbolAddress((void**)&csr_src, g_csr_src);
    cudaGetSymbolAddress((void**)&csr_nrm, g_csr_nrm);
    cudaGetSymbolAddress((void**)&xw,      g_xw);
    cudaGetSymbolAddress((void**)&h,       g_h);
    cudaGetSymbolAddress((void**)&pre,     g_pre);
    cudaGetSymbolAddress((void**)&hseq,    g_hseq);
    cudaGetSymbolAddress((void**)&hstate,  g_hstate);
    cudaGetSymbolAddress((void**)&wihT,    g_wihT);
    cudaGetSymbolAddress((void**)&whhT,    g_whhT);

    const int T = 256;
    // --- CSR build ---
    k_zero_int<<<(N_NODES + T - 1) / T, T>>>(deg, N_NODES);
    k_zero_int<<<(N_NODES + T - 1) / T, T>>>(cur, N_NODES);
    k_deg_int<<<(N_EDGES + T - 1) / T, T>>>(ei, deg);
    k_dinv<<<(N_NODES + T - 1) / T, T>>>(deg, dinv);
    k_scan_blocksum<<<SCAN_NB, SCAN_T>>>(deg, boff);      // boff used as bsum temp
    k_scan_aux<<<1, 32>>>(boff, boff, off);               // in-place: bsum -> exclusive offsets
    k_scan_write<<<SCAN_NB, SCAN_T>>>(deg, boff, off);
    k_csr_fill<<<(N_EDGES + T - 1) / T, T>>>(ei, off, cur, dinv, csr_src, csr_nrm);

    // --- GCN layer 1: xw = x@w1 ; h = relu(gather + self + bias) ---
    k_gcn_mm<IN_DIM><<<N_NODES / 16, 512>>>(x, w1, xw);
    k_gather<<<N_NODES / 8, 256>>>(off, csr_src, csr_nrm, xw, dinv, b1, h);

    // --- GCN layer 2 ---
    k_gcn_mm<GNN_H><<<N_NODES / 16, 512>>>(h, w2, xw);
    k_gather<<<N_NODES / 8, 256>>>(off, csr_src, csr_nrm, xw, dinv, b2, h);

    // --- LSTM layer 0 ---
    k_transpose<<<(GATE4 * GNN_H + T - 1) / T, T>>>(wih0, wihT, GATE4, GNN_H);
    {
        dim3 grid(N_NODES / GM_BM, GATE4 / GM_BN);
        k_gemm_pre<<<grid, 256>>>(h, wihT, bih0, bhh0, pre, GNN_H);
    }
    k_transpose<<<(GATE4 * RNN_H + T - 1) / T, T>>>(whh0, whhT, GATE4, RNN_H);
    k_lstm_layer<<<BATCH / SBM, 128>>>(pre, whhT, hseq, hstate);

    // --- LSTM layer 1 ---
    k_transpose<<<(GATE4 * RNN_H + T - 1) / T, T>>>(wih1, wihT, GATE4, RNN_H);
    {
        dim3 grid(N_NODES / GM_BM, GATE4 / GM_BN);
        k_gemm_pre<<<grid, 256>>>(hseq, wihT, bih1, bhh1, pre, RNN_H);
    }
    k_transpose<<<(GATE4 * RNN_H + T - 1) / T, T>>>(whh1, whhT, GATE4, RNN_H);
    k_lstm_layer<<<BATCH / SBM, 128>>>(pre, whhT, (float*)nullptr, hstate);

    // --- FC head ---
    k_fc<<<(BATCH * OUT_DIM + T - 1) / T, T>>>(hstate, fcw, fcb, out);
}

// round 5
// speedup vs baseline: 3.3833x; 1.5696x over previous
#include <cuda_runtime.h>
#include <cuda_bf16.h>
#include <math.h>
#include <stdint.h>

// ---------------------------------------------------------------------------
// Problem constants
// ---------------------------------------------------------------------------
#define N_NODES 102400
#define N_EDGES 1638400
#define IN_DIM  16
#define GNN_H   64
#define RNN_H   128
#define GATE4   512
#define OUT_DIM 7
#define SEQ_LEN 50
#define BATCH   (N_NODES / SEQ_LEN)   // 2048

#define SCAN_T  512
#define SCAN_NB (N_NODES / SCAN_T)    // 200

// ---------------------------------------------------------------------------
// Scratch (static device globals)
// ---------------------------------------------------------------------------
__device__ float g_dinv[N_NODES];
__device__ int   g_deg [N_NODES];
__device__ int   g_cur [N_NODES];
__device__ int   g_off [N_NODES + 1];
__device__ int   g_boff[SCAN_NB];
__device__ int   g_csr_src[N_EDGES];
__device__ float g_csr_nrm[N_EDGES];
__device__ float g_xw  [N_NODES * GNN_H];
__device__ float g_h   [N_NODES * GNN_H];
__device__ float g_pre [(size_t)N_NODES * GATE4];
__device__ float g_hseq[(size_t)N_NODES * RNN_H];
__device__ float g_hstate[BATCH * RNN_H];
__device__ float g_wihT[RNN_H * GATE4];
__device__ float g_whhT[RNN_H * GATE4];

// ---------------------------------------------------------------------------
// Small helpers
// ---------------------------------------------------------------------------
__device__ __forceinline__ uint32_t cvt_tf32(float x) {
    uint32_t r; asm("cvt.rna.tf32.f32 %0, %1;" : "=r"(r) : "f"(x)); return r;
}
__device__ __forceinline__ float tanh_fast(float x) {
    float y; asm("tanh.approx.f32 %0, %1;" : "=f"(y) : "f"(x)); return y;
}
__device__ __forceinline__ float sigmoid_fast(float x) {
    return 0.5f * tanh_fast(0.5f * x) + 0.5f;
}
__device__ __forceinline__ void mma_tf32(float& d0, float& d1, float& d2, float& d3,
                                         uint32_t a0, uint32_t a1, uint32_t a2, uint32_t a3,
                                         uint32_t b0, uint32_t b1) {
    asm volatile("mma.sync.aligned.m16n8k8.row.col.f32.tf32.tf32.f32 "
                 "{%0,%1,%2,%3}, {%4,%5,%6,%7}, {%8,%9}, {%0,%1,%2,%3};"
                 : "+f"(d0), "+f"(d1), "+f"(d2), "+f"(d3)
                 : "r"(a0), "r"(a1), "r"(a2), "r"(a3), "r"(b0), "r"(b1));
}

// ---------------------------------------------------------------------------
// CSR build
// ---------------------------------------------------------------------------
__global__ void k_zero_int(int* p, int n) {
    int i = blockIdx.x * blockDim.x + threadIdx.x;
    if (i < n) p[i] = 0;
}
__global__ void k_deg_int(const int* __restrict__ ei, int* __restrict__ deg) {
    int e = blockIdx.x * blockDim.x + threadIdx.x;
    if (e >= N_EDGES) return;
    atomicAdd(&deg[ei[N_EDGES + e]], 1);
}
__global__ void k_dinv(const int* __restrict__ deg, float* __restrict__ dinv) {
    int i = blockIdx.x * blockDim.x + threadIdx.x;
    if (i < N_NODES) dinv[i] = rsqrtf((float)(deg[i] + 1));
}
__global__ __launch_bounds__(SCAN_T) void k_scan_blocksum(const int* __restrict__ deg,
                                                          int* __restrict__ bsum) {
    __shared__ int s[SCAN_T];
    int i = threadIdx.x;
    s[i] = deg[blockIdx.x * SCAN_T + i];
    __syncthreads();
    for (int d = SCAN_T / 2; d > 0; d >>= 1) {
        if (i < d) s[i] += s[i + d];
        __syncthreads();
    }
    if (i == 0) bsum[blockIdx.x] = s[0];
}
__global__ void k_scan_aux(int* __restrict__ bsum, int* __restrict__ boff, int* __restrict__ off) {
    if (threadIdx.x == 0) {
        int run = 0;
        for (int b = 0; b < SCAN_NB; ++b) { int v = bsum[b]; boff[b] = run; run += v; }
        off[N_NODES] = run;
    }
}
__global__ __launch_bounds__(SCAN_T) void k_scan_write(const int* __restrict__ deg,
                                                       const int* __restrict__ boff,
                                                       int* __restrict__ off) {
    __shared__ int s[SCAN_T];
    int i = threadIdx.x;
    int g = blockIdx.x * SCAN_T + i;
    int my = deg[g];
    s[i] = my;
    __syncthreads();
    for (int d = 1; d < SCAN_T; d <<= 1) {
        int v = (i >= d) ? s[i - d] : 0;
        __syncthreads();
        s[i] += v;
        __syncthreads();
    }
    off[g] = boff[blockIdx.x] + s[i] - my;
}
__global__ void k_csr_fill(const int* __restrict__ ei, const int* __restrict__ off,
                           int* __restrict__ cur, const float* __restrict__ dinv,
                           int* __restrict__ csr_src, float* __restrict__ csr_nrm) {
    int e = blockIdx.x * blockDim.x + threadIdx.x;
    if (e >= N_EDGES) return;
    int s = ei[e];
    int d = ei[N_EDGES + e];
    int pos = off[d] + atomicAdd(&cur[d], 1);
    csr_src[pos] = s;
    csr_nrm[pos] = dinv[s] * dinv[d];
}

// ---------------------------------------------------------------------------
// GCN dense part: out[N,64] = X[N,K] @ W[K,64]  (fp32, tiny)
// ---------------------------------------------------------------------------
template<int K>
__global__ __launch_bounds__(512) void k_gcn_mm(const float* __restrict__ X,
                                                const float* __restrict__ W,
                                                float* __restrict__ out) {
    __shared__ float sW[K * 64];
    __shared__ float sX[16 * K];
    int tid = threadIdx.x;
    size_t row0 = (size_t)blockIdx.x * 16;
    for (int i = tid; i < K * 64; i += 512) sW[i] = W[i];
    for (int i = tid; i < 16 * K; i += 512) sX[i] = X[row0 * K + i];
    __syncthreads();
    int r = tid >> 6;
    int c = tid & 63;
    float a0 = 0.f, a1 = 0.f;
#pragma unroll
    for (int k = 0; k < K; ++k) {
        float w = sW[k * 64 + c];
        a0 = fmaf(sX[r * K + k],       w, a0);
        a1 = fmaf(sX[(r + 8) * K + k], w, a1);
    }
    out[(row0 + r) * 64 + c]     = a0;
    out[(row0 + r + 8) * 64 + c] = a1;
}

// ---------------------------------------------------------------------------
// Fused gather + self-loop + bias + relu (one warp per dst node)
// ---------------------------------------------------------------------------
__global__ __launch_bounds__(256) void k_gather(const int* __restrict__ off,
                                                const int* __restrict__ csr_src,
                                                const float* __restrict__ csr_nrm,
                                                const float* __restrict__ xw,
                                                const float* __restrict__ dinv,
                                                const float* __restrict__ bias,
                                                float* __restrict__ out) {
    int warp = (blockIdx.x * 256 + threadIdx.x) >> 5;
    int lane = threadIdx.x & 31;
    if (warp >= N_NODES) return;
    int d = warp;
    int c0 = lane * 2;
    float dv = dinv[d];
    float2 self = *(const float2*)&xw[(size_t)d * 64 + c0];
    float2 bb   = *(const float2*)&bias[c0];
    float accx = self.x * dv * dv + bb.x;
    float accy = self.y * dv * dv + bb.y;
    int e0 = off[d], e1 = off[d + 1];
    for (int e = e0; e < e1; ++e) {
        int   s   = csr_src[e];
        float nrm = csr_nrm[e];
        float2 v = *(const float2*)&xw[(size_t)s * 64 + c0];
        accx = fmaf(v.x, nrm, accx);
        accy = fmaf(v.y, nrm, accy);
    }
    float2 o; o.x = fmaxf(accx, 0.f); o.y = fmaxf(accy, 0.f);
    *(float2*)&out[(size_t)d * 64 + c0] = o;
}

// ---------------------------------------------------------------------------
// transpose [R,C] -> [C,R] with tf32 rounding (weights for mma consumers)
// ---------------------------------------------------------------------------
__global__ void k_transpose_tf32(const float* __restrict__ in, float* __restrict__ out,
                                 int R, int C) {
    int i = blockIdx.x * blockDim.x + threadIdx.x;
    if (i >= R * C) return;
    int r = i / C, c = i % C;
    out[c * R + r] = __uint_as_float(cvt_tf32(in[i]));
}

// ---------------------------------------------------------------------------
// tf32 GEMM: C[M,512] = A[M,K] @ Bt[K,512] + b1 + b2
// BM=64, BN=128, BK=16; 256 threads = 8 warps (2m x 4n); warp tile 32x32.
// Bt is pre-rounded tf32; A converted at smem staging.
// ---------------------------------------------------------------------------
__global__ __launch_bounds__(256) void k_gemm_tf32(const float* __restrict__ A,
                                                   const float* __restrict__ Bt,
                                                   const float* __restrict__ b1,
                                                   const float* __restrict__ b2,
                                                   float* __restrict__ C, int K) {
    __shared__ uint32_t As[16][72];
    __shared__ uint32_t Bs[16][136];
    int tid = threadIdx.x;
    int w = tid >> 5, lane = tid & 31;
    int mw = (w >> 2) * 32;   // 0 or 32
    int nw = (w & 3) * 32;    // 0..96
    int g = lane >> 2, t = lane & 3;
    size_t bm = (size_t)blockIdx.x * 64;
    int bn = blockIdx.y * 128;

    float acc[2][4][4];
#pragma unroll
    for (int mt = 0; mt < 2; ++mt)
#pragma unroll
        for (int nt = 0; nt < 4; ++nt)
#pragma unroll
            for (int i = 0; i < 4; ++i) acc[mt][nt][i] = 0.f;

    int ar = tid >> 2, ac = (tid & 3) * 4;
    int brw = tid >> 5, bcf = tid & 31;

    for (int k0 = 0; k0 < K; k0 += 16) {
        float4 av = *(const float4*)(A + (bm + ar) * K + k0 + ac);
        float4 bq0 = *(const float4*)(Bt + (size_t)(k0 + brw) * GATE4 + bn + bcf * 4);
        float4 bq1 = *(const float4*)(Bt + (size_t)(k0 + 8 + brw) * GATE4 + bn + bcf * 4);
        __syncthreads();
        As[ac + 0][ar] = cvt_tf32(av.x);
        As[ac + 1][ar] = cvt_tf32(av.y);
        As[ac + 2][ar] = cvt_tf32(av.z);
        As[ac + 3][ar] = cvt_tf32(av.w);
        {
            uint32_t* d0 = &Bs[brw][bcf * 4];
            d0[0] = __float_as_uint(bq0.x); d0[1] = __float_as_uint(bq0.y);
            d0[2] = __float_as_uint(bq0.z); d0[3] = __float_as_uint(bq0.w);
            uint32_t* d1 = &Bs[brw + 8][bcf * 4];
            d1[0] = __float_as_uint(bq1.x); d1[1] = __float_as_uint(bq1.y);
            d1[2] = __float_as_uint(bq1.z); d1[3] = __float_as_uint(bq1.w);
        }
        __syncthreads();
#pragma unroll
        for (int kt = 0; kt < 2; ++kt) {
            uint32_t af[2][4];
#pragma unroll
            for (int mt = 0; mt < 2; ++mt) {
                int mrow = mw + mt * 16 + g;
                af[mt][0] = As[kt * 8 + t][mrow];
                af[mt][1] = As[kt * 8 + t][mrow + 8];
                af[mt][2] = As[kt * 8 + t + 4][mrow];
                af[mt][3] = As[kt * 8 + t + 4][mrow + 8];
            }
#pragma unroll
            for (int nt = 0; nt < 4; ++nt) {
                int ncol = nw + nt * 8 + g;
                uint32_t bf0 = Bs[kt * 8 + t][ncol];
                uint32_t bf1 = Bs[kt * 8 + t + 4][ncol];
#pragma unroll
                for (int mt = 0; mt < 2; ++mt)
                    mma_tf32(acc[mt][nt][0], acc[mt][nt][1], acc[mt][nt][2], acc[mt][nt][3],
                             af[mt][0], af[mt][1], af[mt][2], af[mt][3], bf0, bf1);
            }
        }
    }
    // epilogue: bias + store
#pragma unroll
    for (int nt = 0; nt < 4; ++nt) {
        int c0 = bn + nw + nt * 8 + 2 * t;
        float bb0 = b1[c0] + b2[c0];
        float bb1 = b1[c0 + 1] + b2[c0 + 1];
#pragma unroll
        for (int mt = 0; mt < 2; ++mt) {
            size_t r0 = bm + mw + mt * 16 + g;
            float2 v0; v0.x = acc[mt][nt][0] + bb0; v0.y = acc[mt][nt][1] + bb1;
            float2 v1; v1.x = acc[mt][nt][2] + bb0; v1.y = acc[mt][nt][3] + bb1;
            *(float2*)(C + r0 * GATE4 + c0)       = v0;
            *(float2*)(C + (r0 + 8) * GATE4 + c0) = v1;
        }
    }
}

// ---------------------------------------------------------------------------
// Persistent tf32-mma LSTM layer.
// 32 blocks x 512 threads; block owns 64 batch rows, all 50 steps.
// Warp w: mw = w>>2 (m-tile of 16 rows), q = w&3 (hidden cols q*32..q*32+31,
// replicated across the 4 gates so i/f/g/o of (row,j) land in one thread).
// whhT (tf32-pre-rounded) streams L2->smem in 2 chunks of 64 k-rows per step.
// smem: sh[64][132] (tf32 h) + Bs[64][520] = 166,912 B dynamic.
// ---------------------------------------------------------------------------
#define L_SBM 64
#define L_NBLK (BATCH / L_SBM)     // 32
#define SH_STRIDE 132
#define BS_STRIDE 520
#define L_SMEM ((64 * SH_STRIDE + 64 * BS_STRIDE) * 4)

__global__ __launch_bounds__(512, 1) void k_lstm_mma(const float* __restrict__ pre,
                                                     const float* __restrict__ whhT,
                                                     float* __restrict__ hseq,
                                                     float* __restrict__ hlast) {
    extern __shared__ uint32_t smem[];
    uint32_t* sh = smem;                      // [64][SH_STRIDE]
    uint32_t* Bs = smem + 64 * SH_STRIDE;     // [64][BS_STRIDE]
    int tid = threadIdx.x;
    int w = tid >> 5, lane = tid & 31;
    int mw = w >> 2;       // 0..3
    int q  = w & 3;        // 0..3
    int g = lane >> 2, t = lane & 3;
    int r0 = mw * 16 + g;                 // local rows r0, r0+8
    int b0 = blockIdx.x * L_SBM;

    float c[16];
#pragma unroll
    for (int i = 0; i < 16; ++i) c[i] = 0.f;
    for (int i = tid; i < 64 * SH_STRIDE; i += 512) sh[i] = 0u;
    __syncthreads();

    for (int st = 0; st < SEQ_LEN; ++st) {
        float acc[16][4];
        // init accumulators from pre-activations (includes biases)
#pragma unroll
        for (int nt = 0; nt < 16; ++nt) {
            int gate = nt >> 2, a = nt & 3;
            int col = gate * 128 + q * 32 + a * 8 + 2 * t;
            size_t base0 = ((size_t)(b0 + r0) * SEQ_LEN + st) * GATE4 + col;
            size_t base1 = ((size_t)(b0 + r0 + 8) * SEQ_LEN + st) * GATE4 + col;
            float2 p0 = *(const float2*)(pre + base0);
            float2 p1 = *(const float2*)(pre + base1);
            acc[nt][0] = p0.x; acc[nt][1] = p0.y; acc[nt][2] = p1.x; acc[nt][3] = p1.y;
        }
        // recurrent matmul: acc += H[64,128] @ whhT[128,512]
#pragma unroll
        for (int ch = 0; ch < 2; ++ch) {
            __syncthreads();
            int kbase = ch * 64;
#pragma unroll
            for (int it = 0; it < 16; ++it) {
                int fid = it * 512 + tid;          // 0..8191 float4s
                int row = fid >> 7;
                int colf = fid & 127;
                float4 v = *(const float4*)(whhT + (size_t)(kbase + row) * GATE4 + colf * 4);
                uint32_t* dst = &Bs[row * BS_STRIDE + colf * 4];
                dst[0] = __float_as_uint(v.x); dst[1] = __float_as_uint(v.y);
                dst[2] = __float_as_uint(v.z); dst[3] = __float_as_uint(v.w);
            }
            __syncthreads();
#pragma unroll
            for (int kt = 0; kt < 8; ++kt) {
                int kg = ch * 64 + kt * 8;
                uint32_t a0 = sh[r0 * SH_STRIDE + kg + t];
                uint32_t a1 = sh[(r0 + 8) * SH_STRIDE + kg + t];
                uint32_t a2 = sh[r0 * SH_STRIDE + kg + t + 4];
                uint32_t a3 = sh[(r0 + 8) * SH_STRIDE + kg + t + 4];
#pragma unroll
                for (int nt = 0; nt < 16; ++nt) {
                    int gate = nt >> 2, a = nt & 3;
                    int col = gate * 128 + q * 32 + a * 8 + g;
                    uint32_t bf0 = Bs[(kt * 8 + t) * BS_STRIDE + col];
                    uint32_t bf1 = Bs[(kt * 8 + t + 4) * BS_STRIDE + col];
                    mma_tf32(acc[nt][0], acc[nt][1], acc[nt][2], acc[nt][3],
                             a0, a1, a2, a3, bf0, bf1);
                }
            }
        }
        __syncthreads();   // all sh reads for this step complete
        // gate nonlinearities + state update (all in registers)
#pragma unroll
        for (int a = 0; a < 4; ++a) {
#pragma unroll
            for (int p = 0; p < 4; ++p) {
                float iv = acc[a][p],      fv = acc[4 + a][p];
                float gv = acc[8 + a][p],  ov = acc[12 + a][p];
                float ig = sigmoid_fast(iv), fg = sigmoid_fast(fv);
                float gg = tanh_fast(gv),    og = sigmoid_fast(ov);
                float cc = fg * c[a * 4 + p] + ig * gg;
                float hh = og * tanh_fast(cc);
                c[a * 4 + p] = cc;
                int rloc = r0 + ((p >> 1) ? 8 : 0);
                int j = q * 32 + a * 8 + 2 * t + (p & 1);
                sh[rloc * SH_STRIDE + j] = cvt_tf32(hh);
                if (hseq)
                    hseq[((size_t)(b0 + rloc) * SEQ_LEN + st) * RNN_H + j] = hh;
                if (st == SEQ_LEN - 1)
                    hlast[(b0 + rloc) * RNN_H + j] = hh;
            }
        }
        __syncthreads();
    }
}

// ---------------------------------------------------------------------------
// FC head
// ---------------------------------------------------------------------------
__global__ void k_fc(const float* __restrict__ h, const float* __restrict__ w,
                     const float* __restrict__ b, float* __restrict__ out) {
    int i = blockIdx.x * blockDim.x + threadIdx.x;
    if (i >= BATCH * OUT_DIM) return;
    int bb = i / OUT_DIM, o = i % OUT_DIM;
    float acc = b[o];
#pragma unroll 4
    for (int k = 0; k < RNN_H; ++k)
        acc = fmaf(h[bb * RNN_H + k], w[k * OUT_DIM + o], acc);
    out[i] = acc;
}

// ---------------------------------------------------------------------------
// Host launcher
// ---------------------------------------------------------------------------
extern "C" void kernel_launch(void* const* d_in, const int* in_sizes, int n_in,
                              void* d_out, int out_size) {
    const float* x  = (const float*)d_in[0];
    const int*   ei = (const int*)d_in[1];   // int32 on device
    int w1i = n_in - 14;
    const float* w1   = (const float*)d_in[w1i + 0];
    const float* b1   = (const float*)d_in[w1i + 1];
    const float* w2   = (const float*)d_in[w1i + 2];
    const float* b2   = (const float*)d_in[w1i + 3];
    const float* wih0 = (const float*)d_in[w1i + 4];
    const float* whh0 = (const float*)d_in[w1i + 5];
    const float* bih0 = (const float*)d_in[w1i + 6];
    const float* bhh0 = (const float*)d_in[w1i + 7];
    const float* wih1 = (const float*)d_in[w1i + 8];
    const float* whh1 = (const float*)d_in[w1i + 9];
    const float* bih1 = (const float*)d_in[w1i + 10];
    const float* bhh1 = (const float*)d_in[w1i + 11];
    const float* fcw  = (const float*)d_in[w1i + 12];
    const float* fcb  = (const float*)d_in[w1i + 13];
    float* out = (float*)d_out;

    float *dinv, *xw, *h, *pre, *hseq, *hstate, *wihT, *whhT, *csr_nrm;
    int *deg, *cur, *off, *boff, *csr_src;
    cudaGetSymbolAddress((void**)&dinv,    g_dinv);
    cudaGetSymbolAddress((void**)&deg,     g_deg);
    cudaGetSymbolAddress((void**)&cur,     g_cur);
    cudaGetSymbolAddress((void**)&off,     g_off);
    cudaGetSymbolAddress((void**)&boff,    g_boff);
    cudaGetSymbolAddress((void**)&csr_src, g_csr_src);
    cudaGetSymbolAddress((void**)&csr_nrm, g_csr_nrm);
    cudaGetSymbolAddress((void**)&xw,      g_xw);
    cudaGetSymbolAddress((void**)&h,       g_h);
    cudaGetSymbolAddress((void**)&pre,     g_pre);
    cudaGetSymbolAddress((void**)&hseq,    g_hseq);
    cudaGetSymbolAddress((void**)&hstate,  g_hstate);
    cudaGetSymbolAddress((void**)&wihT,    g_wihT);
    cudaGetSymbolAddress((void**)&whhT,    g_whhT);

    static bool attr_done = false;
    if (!attr_done) {
        cudaFuncSetAttribute(k_lstm_mma, cudaFuncAttributeMaxDynamicSharedMemorySize, L_SMEM);
        attr_done = true;
    }

    const int T = 256;
    // --- CSR build ---
    k_zero_int<<<(N_NODES + T - 1) / T, T>>>(deg, N_NODES);
    k_zero_int<<<(N_NODES + T - 1) / T, T>>>(cur, N_NODES);
    k_deg_int<<<(N_EDGES + T - 1) / T, T>>>(ei, deg);
    k_dinv<<<(N_NODES + T - 1) / T, T>>>(deg, dinv);
    k_scan_blocksum<<<SCAN_NB, SCAN_T>>>(deg, boff);
    k_scan_aux<<<1, 32>>>(boff, boff, off);
    k_scan_write<<<SCAN_NB, SCAN_T>>>(deg, boff, off);
    k_csr_fill<<<(N_EDGES + T - 1) / T, T>>>(ei, off, cur, dinv, csr_src, csr_nrm);

    // --- GCN layer 1 ---
    k_gcn_mm<IN_DIM><<<N_NODES / 16, 512>>>(x, w1, xw);
    k_gather<<<N_NODES / 8, 256>>>(off, csr_src, csr_nrm, xw, dinv, b1, h);

    // --- GCN layer 2 ---
    k_gcn_mm<GNN_H><<<N_NODES / 16, 512>>>(h, w2, xw);
    k_gather<<<N_NODES / 8, 256>>>(off, csr_src, csr_nrm, xw, dinv, b2, h);

    // --- LSTM layer 0 ---
    k_transpose_tf32<<<(GATE4 * GNN_H + T - 1) / T, T>>>(wih0, wihT, GATE4, GNN_H);
    {
        dim3 grid(N_NODES / 64, GATE4 / 128);
        k_gemm_tf32<<<grid, 256>>>(h, wihT, bih0, bhh0, pre, GNN_H);
    }
    k_transpose_tf32<<<(GATE4 * RNN_H + T - 1) / T, T>>>(whh0, whhT, GATE4, RNN_H);
    k_lstm_mma<<<L_NBLK, 512, L_SMEM>>>(pre, whhT, hseq, hstate);

    // --- LSTM layer 1 ---
    k_transpose_tf32<<<(GATE4 * RNN_H + T - 1) / T, T>>>(wih1, wihT, GATE4, RNN_H);
    {
        dim3 grid(N_NODES / 64, GATE4 / 128);
        k_gemm_tf32<<<grid, 256>>>(hseq, wihT, bih1, bhh1, pre, RNN_H);
    }
    k_transpose_tf32<<<(GATE4 * RNN_H + T - 1) / T, T>>>(whh1, whhT, GATE4, RNN_H);
    k_lstm_mma<<<L_NBLK, 512, L_SMEM>>>(pre, whhT, (float*)nullptr, hstate);

    // --- FC head ---
    k_fc<<<(BATCH * OUT_DIM + T - 1) / T, T>>>(hstate, fcw, fcb, out);
}

// round 6
// speedup vs baseline: 5.4247x; 1.6034x over previous
#include <cuda_runtime.h>
#include <cuda_bf16.h>
#include <math.h>
#include <stdint.h>

#define N_NODES 102400
#define N_EDGES 1638400
#define IN_DIM  16
#define GNN_H   64
#define RNN_H   128
#define GATE4   512
#define OUT_DIM 7
#define SEQ_LEN 50
#define BATCH   (N_NODES / SEQ_LEN)   // 2048

#define SCAN_T  512
#define SCAN_NB (N_NODES / SCAN_T)    // 200

// ---------------------------------------------------------------------------
__device__ float g_dinv[N_NODES];
__device__ int   g_deg [N_NODES];
__device__ int   g_cur [N_NODES];
__device__ int   g_off [N_NODES + 1];
__device__ int   g_boff[SCAN_NB];
__device__ int   g_csr_src[N_EDGES];
__device__ float g_csr_nrm[N_EDGES];
__device__ float g_xw  [N_NODES * GNN_H];
__device__ float g_h   [N_NODES * GNN_H];
__device__ float g_pre [(size_t)N_NODES * GATE4];
__device__ float g_hseq[(size_t)N_NODES * RNN_H];
__device__ float g_hstate[BATCH * RNN_H];
__device__ float g_wihT[RNN_H * GATE4];
__device__ float g_whhT[RNN_H * GATE4];

// ---------------------------------------------------------------------------
__device__ __forceinline__ uint32_t cvt_tf32(float x) {
    uint32_t r; asm("cvt.rna.tf32.f32 %0, %1;" : "=r"(r) : "f"(x)); return r;
}
__device__ __forceinline__ float tanh_fast(float x) {
    float y; asm("tanh.approx.f32 %0, %1;" : "=f"(y) : "f"(x)); return y;
}
__device__ __forceinline__ float sigmoid_fast(float x) {
    return 0.5f * tanh_fast(0.5f * x) + 0.5f;
}
__device__ __forceinline__ void mma_tf32(float& d0, float& d1, float& d2, float& d3,
                                         uint32_t a0, uint32_t a1, uint32_t a2, uint32_t a3,
                                         uint32_t b0, uint32_t b1) {
    asm volatile("mma.sync.aligned.m16n8k8.row.col.f32.tf32.tf32.f32 "
                 "{%0,%1,%2,%3}, {%4,%5,%6,%7}, {%8,%9}, {%0,%1,%2,%3};"
                 : "+f"(d0), "+f"(d1), "+f"(d2), "+f"(d3)
                 : "r"(a0), "r"(a1), "r"(a2), "r"(a3), "r"(b0), "r"(b1));
}
#define CP_ASYNC16(dst, src) \
    asm volatile("cp.async.cg.shared.global [%0], [%1], 16;" :: "r"(dst), "l"(src))
#define CP_COMMIT() asm volatile("cp.async.commit_group;")
#define CP_WAIT0()  asm volatile("cp.async.wait_group 0;" ::: "memory")

// ---------------------------------------------------------------------------
// CSR build
// ---------------------------------------------------------------------------
__global__ void k_zero_int(int* p, int n) {
    int i = blockIdx.x * blockDim.x + threadIdx.x;
    if (i < n) p[i] = 0;
}
__global__ void k_deg_int(const int* __restrict__ ei, int* __restrict__ deg) {
    int e = blockIdx.x * blockDim.x + threadIdx.x;
    if (e >= N_EDGES) return;
    atomicAdd(&deg[ei[N_EDGES + e]], 1);
}
__global__ void k_dinv(const int* __restrict__ deg, float* __restrict__ dinv) {
    int i = blockIdx.x * blockDim.x + threadIdx.x;
    if (i < N_NODES) dinv[i] = rsqrtf((float)(deg[i] + 1));
}
__global__ __launch_bounds__(SCAN_T) void k_scan_blocksum(const int* __restrict__ deg,
                                                          int* __restrict__ bsum) {
    __shared__ int s[SCAN_T];
    int i = threadIdx.x;
    s[i] = deg[blockIdx.x * SCAN_T + i];
    __syncthreads();
    for (int d = SCAN_T / 2; d > 0; d >>= 1) {
        if (i < d) s[i] += s[i + d];
        __syncthreads();
    }
    if (i == 0) bsum[blockIdx.x] = s[0];
}
__global__ void k_scan_aux(int* __restrict__ bsum, int* __restrict__ boff, int* __restrict__ off) {
    if (threadIdx.x == 0) {
        int run = 0;
        for (int b = 0; b < SCAN_NB; ++b) { int v = bsum[b]; boff[b] = run; run += v; }
        off[N_NODES] = run;
    }
}
__global__ __launch_bounds__(SCAN_T) void k_scan_write(const int* __restrict__ deg,
                                                       const int* __restrict__ boff,
                                                       int* __restrict__ off) {
    __shared__ int s[SCAN_T];
    int i = threadIdx.x;
    int g = blockIdx.x * SCAN_T + i;
    int my = deg[g];
    s[i] = my;
    __syncthreads();
    for (int d = 1; d < SCAN_T; d <<= 1) {
        int v = (i >= d) ? s[i - d] : 0;
        __syncthreads();
        s[i] += v;
        __syncthreads();
    }
    off[g] = boff[blockIdx.x] + s[i] - my;
}
__global__ void k_csr_fill(const int* __restrict__ ei, const int* __restrict__ off,
                           int* __restrict__ cur, const float* __restrict__ dinv,
                           int* __restrict__ csr_src, float* __restrict__ csr_nrm) {
    int e = blockIdx.x * blockDim.x + threadIdx.x;
    if (e >= N_EDGES) return;
    int s = ei[e];
    int d = ei[N_EDGES + e];
    int pos = off[d] + atomicAdd(&cur[d], 1);
    csr_src[pos] = s;
    csr_nrm[pos] = dinv[s] * dinv[d];
}

// ---------------------------------------------------------------------------
// GCN dense part
// ---------------------------------------------------------------------------
template<int K>
__global__ __launch_bounds__(512) void k_gcn_mm(const float* __restrict__ X,
                                                const float* __restrict__ W,
                                                float* __restrict__ out) {
    __shared__ float sW[K * 64];
    __shared__ float sX[16 * K];
    int tid = threadIdx.x;
    size_t row0 = (size_t)blockIdx.x * 16;
    for (int i = tid; i < K * 64; i += 512) sW[i] = W[i];
    for (int i = tid; i < 16 * K; i += 512) sX[i] = X[row0 * K + i];
    __syncthreads();
    int r = tid >> 6;
    int c = tid & 63;
    float a0 = 0.f, a1 = 0.f;
#pragma unroll
    for (int k = 0; k < K; ++k) {
        float w = sW[k * 64 + c];
        a0 = fmaf(sX[r * K + k],       w, a0);
        a1 = fmaf(sX[(r + 8) * K + k], w, a1);
    }
    out[(row0 + r) * 64 + c]     = a0;
    out[(row0 + r + 8) * 64 + c] = a1;
}

// ---------------------------------------------------------------------------
// Fused gather + self-loop + bias + relu (one warp per dst node)
// ---------------------------------------------------------------------------
__global__ __launch_bounds__(256) void k_gather(const int* __restrict__ off,
                                                const int* __restrict__ csr_src,
                                                const float* __restrict__ csr_nrm,
                                                const float* __restrict__ xw,
                                                const float* __restrict__ dinv,
                                                const float* __restrict__ bias,
                                                float* __restrict__ out) {
    int warp = (blockIdx.x * 256 + threadIdx.x) >> 5;
    int lane = threadIdx.x & 31;
    if (warp >= N_NODES) return;
    int d = warp;
    int c0 = lane * 2;
    float dv = dinv[d];
    float2 self = *(const float2*)&xw[(size_t)d * 64 + c0];
    float2 bb   = *(const float2*)&bias[c0];
    float accx = self.x * dv * dv + bb.x;
    float accy = self.y * dv * dv + bb.y;
    int e0 = off[d], e1 = off[d + 1];
    for (int e = e0; e < e1; ++e) {
        int   s   = csr_src[e];
        float nrm = csr_nrm[e];
        float2 v = *(const float2*)&xw[(size_t)s * 64 + c0];
        accx = fmaf(v.x, nrm, accx);
        accy = fmaf(v.y, nrm, accy);
    }
    float2 o; o.x = fmaxf(accx, 0.f); o.y = fmaxf(accy, 0.f);
    *(float2*)&out[(size_t)d * 64 + c0] = o;
}

// ---------------------------------------------------------------------------
// transpose with tf32 rounding
// ---------------------------------------------------------------------------
__global__ void k_transpose_tf32(const float* __restrict__ in, float* __restrict__ out,
                                 int R, int C) {
    int i = blockIdx.x * blockDim.x + threadIdx.x;
    if (i >= R * C) return;
    int r = i / C, c = i % C;
    out[c * R + r] = __uint_as_float(cvt_tf32(in[i]));
}

// ---------------------------------------------------------------------------
// tf32 GEMM: C[M,512] = A[M,K] @ Bt[K,512] + b1 + b2
// ---------------------------------------------------------------------------
__global__ __launch_bounds__(256) void k_gemm_tf32(const float* __restrict__ A,
                                                   const float* __restrict__ Bt,
                                                   const float* __restrict__ b1,
                                                   const float* __restrict__ b2,
                                                   float* __restrict__ C, int K) {
    __shared__ uint32_t As[16][72];
    __shared__ uint32_t Bs[16][136];
    int tid = threadIdx.x;
    int w = tid >> 5, lane = tid & 31;
    int mw = (w >> 2) * 32;
    int nw = (w & 3) * 32;
    int g = lane >> 2, t = lane & 3;
    size_t bm = (size_t)blockIdx.x * 64;
    int bn = blockIdx.y * 128;

    float acc[2][4][4];
#pragma unroll
    for (int mt = 0; mt < 2; ++mt)
#pragma unroll
        for (int nt = 0; nt < 4; ++nt)
#pragma unroll
            for (int i = 0; i < 4; ++i) acc[mt][nt][i] = 0.f;

    int ar = tid >> 2, ac = (tid & 3) * 4;
    int brw = tid >> 5, bcf = tid & 31;

    for (int k0 = 0; k0 < K; k0 += 16) {
        float4 av = *(const float4*)(A + (bm + ar) * K + k0 + ac);
        float4 bq0 = *(const float4*)(Bt + (size_t)(k0 + brw) * GATE4 + bn + bcf * 4);
        float4 bq1 = *(const float4*)(Bt + (size_t)(k0 + 8 + brw) * GATE4 + bn + bcf * 4);
        __syncthreads();
        As[ac + 0][ar] = cvt_tf32(av.x);
        As[ac + 1][ar] = cvt_tf32(av.y);
        As[ac + 2][ar] = cvt_tf32(av.z);
        As[ac + 3][ar] = cvt_tf32(av.w);
        {
            uint32_t* d0 = &Bs[brw][bcf * 4];
            d0[0] = __float_as_uint(bq0.x); d0[1] = __float_as_uint(bq0.y);
            d0[2] = __float_as_uint(bq0.z); d0[3] = __float_as_uint(bq0.w);
            uint32_t* d1 = &Bs[brw + 8][bcf * 4];
            d1[0] = __float_as_uint(bq1.x); d1[1] = __float_as_uint(bq1.y);
            d1[2] = __float_as_uint(bq1.z); d1[3] = __float_as_uint(bq1.w);
        }
        __syncthreads();
#pragma unroll
        for (int kt = 0; kt < 2; ++kt) {
            uint32_t af[2][4];
#pragma unroll
            for (int mt = 0; mt < 2; ++mt) {
                int mrow = mw + mt * 16 + g;
                af[mt][0] = As[kt * 8 + t][mrow];
                af[mt][1] = As[kt * 8 + t][mrow + 8];
                af[mt][2] = As[kt * 8 + t + 4][mrow];
                af[mt][3] = As[kt * 8 + t + 4][mrow + 8];
            }
#pragma unroll
            for (int nt = 0; nt < 4; ++nt) {
                int ncol = nw + nt * 8 + g;
                uint32_t bf0 = Bs[kt * 8 + t][ncol];
                uint32_t bf1 = Bs[kt * 8 + t + 4][ncol];
#pragma unroll
                for (int mt = 0; mt < 2; ++mt)
                    mma_tf32(acc[mt][nt][0], acc[mt][nt][1], acc[mt][nt][2], acc[mt][nt][3],
                             af[mt][0], af[mt][1], af[mt][2], af[mt][3], bf0, bf1);
            }
        }
    }
#pragma unroll
    for (int nt = 0; nt < 4; ++nt) {
        int c0 = bn + nw + nt * 8 + 2 * t;
        float bb0 = b1[c0] + b2[c0];
        float bb1 = b1[c0 + 1] + b2[c0 + 1];
#pragma unroll
        for (int mt = 0; mt < 2; ++mt) {
            size_t r0 = bm + mw + mt * 16 + g;
            float2 v0; v0.x = acc[mt][nt][0] + bb0; v0.y = acc[mt][nt][1] + bb1;
            float2 v1; v1.x = acc[mt][nt][2] + bb0; v1.y = acc[mt][nt][3] + bb1;
            *(float2*)(C + r0 * GATE4 + c0)       = v0;
            *(float2*)(C + (r0 + 8) * GATE4 + c0) = v1;
        }
    }
}

// ---------------------------------------------------------------------------
// Persistent tf32-mma LSTM layer, 64 blocks x 512 threads, SBM=32 rows/block.
// 16 warps = 2m x 8q. Warp: 16 rows x 64 gate-cols (16 per gate, interleaved
// so i/f/g/o of (row,j) sit in one thread). whhT streams L2->smem in 4 chunks
// of 32 k-rows with cp.async double buffering.
// ---------------------------------------------------------------------------
#define L_SBM 32
#define L_NBLK (BATCH / L_SBM)     // 64
#define SH_STRIDE 132
#define BS_STRIDE 520
#define L_SMEM ((L_SBM * SH_STRIDE + 2 * 32 * BS_STRIDE) * 4)   // 150,016 B

__global__ __launch_bounds__(512, 1) void k_lstm_mma(const float* __restrict__ pre,
                                                     const float* __restrict__ whhT,
                                                     float* __restrict__ hseq,
                                                     float* __restrict__ hlast) {
    extern __shared__ uint32_t smem[];
    uint32_t* sh = smem;                          // [32][SH_STRIDE]
    uint32_t* Bs = smem + L_SBM * SH_STRIDE;      // [2][32][BS_STRIDE]
    int tid = threadIdx.x;
    int w = tid >> 5, lane = tid & 31;
    int mhalf = w >> 3;        // 0..1
    int q     = w & 7;         // 0..7
    int g = lane >> 2, t = lane & 3;
    int r0 = mhalf * 16 + g;   // rows r0, r0+8
    int b0 = blockIdx.x * L_SBM;

    uint32_t bs_smem[2];
    bs_smem[0] = (uint32_t)__cvta_generic_to_shared(Bs);
    bs_smem[1] = (uint32_t)__cvta_generic_to_shared(Bs + 32 * BS_STRIDE);

    float c[8];
#pragma unroll
    for (int i = 0; i < 8; ++i) c[i] = 0.f;
    for (int i = tid; i < L_SBM * SH_STRIDE; i += 512) sh[i] = 0u;
    __syncthreads();

    for (int st = 0; st < SEQ_LEN; ++st) {
        // init accumulators from pre-activations
        float acc[8][4];
#pragma unroll
        for (int nt = 0; nt < 8; ++nt) {
            int gate = nt >> 1, a = nt & 1;
            int col = gate * 128 + q * 16 + a * 8 + 2 * t;
            size_t base0 = ((size_t)(b0 + r0) * SEQ_LEN + st) * GATE4 + col;
            size_t base1 = ((size_t)(b0 + r0 + 8) * SEQ_LEN + st) * GATE4 + col;
            float2 p0 = *(const float2*)(pre + base0);
            float2 p1 = *(const float2*)(pre + base1);
            acc[nt][0] = p0.x; acc[nt][1] = p0.y; acc[nt][2] = p1.x; acc[nt][3] = p1.y;
        }
        // prologue: issue chunk 0
        {
#pragma unroll
            for (int it = 0; it < 8; ++it) {
                int fid = it * 512 + tid;
                int row = fid >> 7, colf = fid & 127;
                CP_ASYNC16(bs_smem[0] + (uint32_t)(row * BS_STRIDE + colf * 4) * 4,
                           whhT + (size_t)row * GATE4 + colf * 4);
            }
            CP_COMMIT();
        }
#pragma unroll
        for (int ch = 0; ch < 4; ++ch) {
            CP_WAIT0();
            __syncthreads();            // chunk ch visible; prior reads of other buf done
            if (ch < 3) {               // issue chunk ch+1 into other buffer
                int kbase = (ch + 1) * 32;
                uint32_t dstb = bs_smem[(ch + 1) & 1];
#pragma unroll
                for (int it = 0; it < 8; ++it) {
                    int fid = it * 512 + tid;
                    int row = fid >> 7, colf = fid & 127;
                    CP_ASYNC16(dstb + (uint32_t)(row * BS_STRIDE + colf * 4) * 4,
                               whhT + (size_t)(kbase + row) * GATE4 + colf * 4);
                }
                CP_COMMIT();
            }
            const uint32_t* Bc = Bs + (ch & 1) * 32 * BS_STRIDE;
#pragma unroll
            for (int kt = 0; kt < 4; ++kt) {
                int kg = ch * 32 + kt * 8;
                uint32_t a0 = sh[r0 * SH_STRIDE + kg + t];
                uint32_t a1 = sh[(r0 + 8) * SH_STRIDE + kg + t];
                uint32_t a2 = sh[r0 * SH_STRIDE + kg + t + 4];
                uint32_t a3 = sh[(r0 + 8) * SH_STRIDE + kg + t + 4];
#pragma unroll
                for (int nt = 0; nt < 8; ++nt) {
                    int gate = nt >> 1, a = nt & 1;
                    int col = gate * 128 + q * 16 + a * 8 + g;
                    uint32_t bf0 = Bc[(kt * 8 + t) * BS_STRIDE + col];
                    uint32_t bf1 = Bc[(kt * 8 + t + 4) * BS_STRIDE + col];
                    mma_tf32(acc[nt][0], acc[nt][1], acc[nt][2], acc[nt][3],
                             a0, a1, a2, a3, bf0, bf1);
                }
            }
        }
        __syncthreads();   // all sh/Bs reads complete before state update rewrites sh
        // gate nonlinearities + state update
#pragma unroll
        for (int a = 0; a < 2; ++a) {
#pragma unroll
            for (int p = 0; p < 4; ++p) {
                float iv = acc[a][p],     fv = acc[2 + a][p];
                float gv = acc[4 + a][p], ov = acc[6 + a][p];
                float ig = sigmoid_fast(iv), fg = sigmoid_fast(fv);
                float gg = tanh_fast(gv),    og = sigmoid_fast(ov);
                float cc = fg * c[a * 4 + p] + ig * gg;
                float hh = og * tanh_fast(cc);
                c[a * 4 + p] = cc;
                int rloc = r0 + ((p >> 1) ? 8 : 0);
                int j = q * 16 + a * 8 + 2 * t + (p & 1);
                sh[rloc * SH_STRIDE + j] = cvt_tf32(hh);
                if (hseq)
                    hseq[((size_t)(b0 + rloc) * SEQ_LEN + st) * RNN_H + j] = hh;
                if (st == SEQ_LEN - 1)
                    hlast[(b0 + rloc) * RNN_H + j] = hh;
            }
        }
        __syncthreads();
    }
}

// ---------------------------------------------------------------------------
// FC head
// ---------------------------------------------------------------------------
__global__ void k_fc(const float* __restrict__ h, const float* __restrict__ w,
                     const float* __restrict__ b, float* __restrict__ out) {
    int i = blockIdx.x * blockDim.x + threadIdx.x;
    if (i >= BATCH * OUT_DIM) return;
    int bb = i / OUT_DIM, o = i % OUT_DIM;
    float acc = b[o];
#pragma unroll 4
    for (int k = 0; k < RNN_H; ++k)
        acc = fmaf(h[bb * RNN_H + k], w[k * OUT_DIM + o], acc);
    out[i] = acc;
}

// ---------------------------------------------------------------------------
// Host launcher
// ---------------------------------------------------------------------------
extern "C" void kernel_launch(void* const* d_in, const int* in_sizes, int n_in,
                              void* d_out, int out_size) {
    const float* x  = (const float*)d_in[0];
    const int*   ei = (const int*)d_in[1];
    int w1i = n_in - 14;
    const float* w1   = (const float*)d_in[w1i + 0];
    const float* b1   = (const float*)d_in[w1i + 1];
    const float* w2   = (const float*)d_in[w1i + 2];
    const float* b2   = (const float*)d_in[w1i + 3];
    const float* wih0 = (const float*)d_in[w1i + 4];
    const float* whh0 = (const float*)d_in[w1i + 5];
    const float* bih0 = (const float*)d_in[w1i + 6];
    const float* bhh0 = (const float*)d_in[w1i + 7];
    const float* wih1 = (const float*)d_in[w1i + 8];
    const float* whh1 = (const float*)d_in[w1i + 9];
    const float* bih1 = (const float*)d_in[w1i + 10];
    const float* bhh1 = (const float*)d_in[w1i + 11];
    const float* fcw  = (const float*)d_in[w1i + 12];
    const float* fcb  = (const float*)d_in[w1i + 13];
    float* out = (float*)d_out;

    float *dinv, *xw, *h, *pre, *hseq, *hstate, *wihT, *whhT, *csr_nrm;
    int *deg, *cur, *off, *boff, *csr_src;
    cudaGetSymbolAddress((void**)&dinv,    g_dinv);
    cudaGetSymbolAddress((void**)&deg,     g_deg);
    cudaGetSymbolAddress((void**)&cur,     g_cur);
    cudaGetSymbolAddress((void**)&off,     g_off);
    cudaGetSymbolAddress((void**)&boff,    g_boff);
    cudaGetSymbolAddress((void**)&csr_src, g_csr_src);
    cudaGetSymbolAddress((void**)&csr_nrm, g_csr_nrm);
    cudaGetSymbolAddress((void**)&xw,      g_xw);
    cudaGetSymbolAddress((void**)&h,       g_h);
    cudaGetSymbolAddress((void**)&pre,     g_pre);
    cudaGetSymbolAddress((void**)&hseq,    g_hseq);
    cudaGetSymbolAddress((void**)&hstate,  g_hstate);
    cudaGetSymbolAddress((void**)&wihT,    g_wihT);
    cudaGetSymbolAddress((void**)&whhT,    g_whhT);

    static bool attr_done = false;
    if (!attr_done) {
        cudaFuncSetAttribute(k_lstm_mma, cudaFuncAttributeMaxDynamicSharedMemorySize, L_SMEM);
        attr_done = true;
    }

    const int T = 256;
    // --- CSR build ---
    k_zero_int<<<(N_NODES + T - 1) / T, T>>>(deg, N_NODES);
    k_zero_int<<<(N_NODES + T - 1) / T, T>>>(cur, N_NODES);
    k_deg_int<<<(N_EDGES + T - 1) / T, T>>>(ei, deg);
    k_dinv<<<(N_NODES + T - 1) / T, T>>>(deg, dinv);
    k_scan_blocksum<<<SCAN_NB, SCAN_T>>>(deg, boff);
    k_scan_aux<<<1, 32>>>(boff, boff, off);
    k_scan_write<<<SCAN_NB, SCAN_T>>>(deg, boff, off);
    k_csr_fill<<<(N_EDGES + T - 1) / T, T>>>(ei, off, cur, dinv, csr_src, csr_nrm);

    // --- GCN layer 1 ---
    k_gcn_mm<IN_DIM><<<N_NODES / 16, 512>>>(x, w1, xw);
    k_gather<<<N_NODES / 8, 256>>>(off, csr_src, csr_nrm, xw, dinv, b1, h);

    // --- GCN layer 2 ---
    k_gcn_mm<GNN_H><<<N_NODES / 16, 512>>>(h, w2, xw);
    k_gather<<<N_NODES / 8, 256>>>(off, csr_src, csr_nrm, xw, dinv, b2, h);

    // --- LSTM layer 0 ---
    k_transpose_tf32<<<(GATE4 * GNN_H + T - 1) / T, T>>>(wih0, wihT, GATE4, GNN_H);
    {
        dim3 grid(N_NODES / 64, GATE4 / 128);
        k_gemm_tf32<<<grid, 256>>>(h, wihT, bih0, bhh0, pre, GNN_H);
    }
    k_transpose_tf32<<<(GATE4 * RNN_H + T - 1) / T, T>>>(whh0, whhT, GATE4, RNN_H);
    k_lstm_mma<<<L_NBLK, 512, L_SMEM>>>(pre, whhT, hseq, hstate);

    // --- LSTM layer 1 ---
    k_transpose_tf32<<<(GATE4 * RNN_H + T - 1) / T, T>>>(wih1, wihT, GATE4, RNN_H);
    {
        dim3 grid(N_NODES / 64, GATE4 / 128);
        k_gemm_tf32<<<grid, 256>>>(hseq, wihT, bih1, bhh1, pre, RNN_H);
    }
    k_transpose_tf32<<<(GATE4 * RNN_H + T - 1) / T, T>>>(whh1, whhT, GATE4, RNN_H);
    k_lstm_mma<<<L_NBLK, 512, L_SMEM>>>(pre, whhT, (float*)nullptr, hstate);

    // --- FC head ---
    k_fc<<<(BATCH * OUT_DIM + T - 1) / T, T>>>(hstate, fcw, fcb, out);
}